// round 14
// baseline (speedup 1.0000x reference)
#include <cuda_runtime.h>
#include <cuda_bf16.h>
#include <cuda_fp16.h>
#include <math.h>
#include <stdint.h>

// ---------------------------------------------------------------------------
// EnhancedTransformerBlock  B=8 S=1024 H=1024 nh=16 hd=64
// fp16 mma.sync GEMMs (128x128, 3-stage cp.async, 1 sync/chunk, 2 CTA/SM)
// + fused flash-attn + 1-launch prep
// ---------------------------------------------------------------------------

#define Bsz   8
#define Ssz   1024
#define Hsz   1024
#define NH    16
#define HD    64
#define Mrows (Bsz*Ssz)          // 8192
#define HF    (4*Hsz)            // 4096
#define HG    (Hsz/2)            // 512
#define H3    (3*Hsz)            // 3072

// ------------------------- scratch (device globals) ------------------------
__device__ __half g_xh  [(size_t)Mrows*Hsz];
__device__ __half g_QKV [(size_t)Mrows*H3];       // packed Q|K|V rows
__device__ __half g_ctx [(size_t)Mrows*Hsz];
__device__ float  g_xr  [(size_t)Mrows*Hsz];
__device__ float  g_x1  [(size_t)Mrows*Hsz];
__device__ __half g_x1h [(size_t)Mrows*Hsz];
__device__ __half g_h   [(size_t)Mrows*HF];
__device__ float  g_f   [(size_t)Mrows*Hsz];
__device__ __half g_g1  [(size_t)Mrows*HG];
__device__ float  g_g   [(size_t)Mrows*Hsz];
// transposed fp16 weights ([N][K] K-major)
__device__ __half g_WqkvT[(size_t)H3*Hsz];        // rows: [Wq*0.125 | Wk | Wv]
__device__ float  g_bqkv [H3];
__device__ __half g_WoT [(size_t)Hsz*Hsz];
__device__ __half g_fw1T[(size_t)Hsz*HF];
__device__ __half g_fw2T[(size_t)HF*Hsz];
__device__ __half g_gw1T[(size_t)Hsz*HG];
__device__ __half g_gw2T[(size_t)HG*Hsz];

// ------------------------------ helpers ------------------------------------
__device__ __forceinline__ uint32_t pack_h2(float lo, float hi) {
    __half2 h = __floats2half2_rn(lo, hi);
    return *(uint32_t*)&h;
}
__device__ __forceinline__ void mma_f16(float* c, const uint32_t* a, const uint32_t* b) {
    asm volatile(
        "mma.sync.aligned.m16n8k16.row.col.f32.f16.f16.f32 "
        "{%0,%1,%2,%3}, {%4,%5,%6,%7}, {%8,%9}, {%0,%1,%2,%3};"
        : "+f"(c[0]), "+f"(c[1]), "+f"(c[2]), "+f"(c[3])
        : "r"(a[0]), "r"(a[1]), "r"(a[2]), "r"(a[3]), "r"(b[0]), "r"(b[1]));
}
__device__ __forceinline__ int sw128(int byte) {
    return byte ^ ((byte >> 3) & 0x70);
}
__device__ __forceinline__ uint32_t smem_addr(const void* p) {
    return (uint32_t)__cvta_generic_to_shared(p);
}
__device__ __forceinline__ void cp16(uint32_t dst, const void* src) {
    asm volatile("cp.async.cg.shared.global [%0], [%1], 16;" :: "r"(dst), "l"(src));
}
__device__ __forceinline__ void cp_commit() { asm volatile("cp.async.commit_group;" ::: "memory"); }
template<int N> __device__ __forceinline__ void cp_wait() {
    asm volatile("cp.async.wait_group %0;" :: "n"(N) : "memory");
}
__device__ __forceinline__ void ldmx4(uint32_t* r, uint32_t addr) {
    asm volatile("ldmatrix.sync.aligned.m8n8.x4.shared.b16 {%0,%1,%2,%3}, [%4];"
        : "=r"(r[0]), "=r"(r[1]), "=r"(r[2]), "=r"(r[3]) : "r"(addr));
}

// ----------------------------- FP16 GEMM -----------------------------------
// C[m,n] = act(sum_k A[m,k]*B[n,k] + bias[n]) (+resid)
// A fp16 [M,K] K-major, B fp16 [N,K] K-major; tile 128x128, k-chunk 64.
// 3-stage cp.async pipeline, one __syncthreads per chunk.
// act: 0 none, 1 gelu, 2 relu, 3 sigmoid
template<typename CT>
__global__ __launch_bounds__(256, 2)
void mma_gemm(const __half* __restrict__ A, int lda,
              const __half* __restrict__ B, int ldb,
              CT* __restrict__ C, int ldc,
              const float* __restrict__ bias, const float* __restrict__ resid,
              int K, int act)
{
    extern __shared__ char sm[];   // 3 stages x (16KB A + 16KB B)

    const int tid = threadIdx.x, wid = tid >> 5, lane = tid & 31;
    const int gid = lane >> 2, tig = lane & 3;
    const int warpm = wid & 1, warpn = wid >> 1;

    const int m0 = blockIdx.y * 128;
    const int n0 = blockIdx.x * 128;

    float c[4][4][4];
    #pragma unroll
    for (int mi = 0; mi < 4; mi++)
        #pragma unroll
        for (int ni = 0; ni < 4; ni++)
            #pragma unroll
            for (int e = 0; e < 4; e++) c[mi][ni][e] = 0.f;

    // ---- hoisted staging addresses ----
    const int sr = tid >> 3, scq = tid & 7;     // row base 0..31, 16B col 0..7
    const __half* Ap[4]; const __half* Bp[4]; int swb[4];
    #pragma unroll
    for (int i = 0; i < 4; i++) {
        const int r = sr + i * 32;
        Ap[i]  = A + (size_t)(m0 + r) * lda + scq * 8;
        Bp[i]  = B + (size_t)(n0 + r) * ldb + scq * 8;
        swb[i] = sw128(r * 128 + scq * 16);
    }
    const uint32_t smem_base = smem_addr(sm);

    auto stage = [&](int kt, int st) {
        const uint32_t sa = smem_base + st * 32768;
        #pragma unroll
        for (int i = 0; i < 4; i++) {
            cp16(sa + swb[i],         Ap[i] + kt);
            cp16(sa + 16384 + swb[i], Bp[i] + kt);
        }
        cp_commit();
    };

    const int nch = K >> 6;
    stage(0, 0);
    stage(64, 1);

    int st = 0;                                  // stage index of current chunk
    for (int ch = 0; ch < nch; ch++) {
        if (ch < nch - 1) cp_wait<1>(); else cp_wait<0>();
        __syncthreads();
        if (ch + 2 < nch) {
            int ns = st + 2; if (ns >= 3) ns -= 3;
            stage((ch + 2) << 6, ns);
        }

        const char* As = sm + st * 32768;
        const char* Bs = As + 16384;
        #pragma unroll
        for (int ks = 0; ks < 4; ks++) {
            uint32_t a[4][4], b[4][2];
            #pragma unroll
            for (int mi = 0; mi < 4; mi++) {
                int row = warpm * 64 + mi * 16 + (lane & 15);
                int colb = ks * 32 + ((lane & 16) ? 16 : 0);
                ldmx4(a[mi], smem_addr(As + sw128(row * 128 + colb)));
            }
            #pragma unroll
            for (int np = 0; np < 2; np++) {
                int row = warpn * 32 + np * 16 + (lane & 7) + ((lane & 16) ? 8 : 0);
                int colb = ks * 32 + ((lane & 8) ? 16 : 0);
                uint32_t t[4];
                ldmx4(t, smem_addr(Bs + sw128(row * 128 + colb)));
                b[2*np][0] = t[0]; b[2*np][1] = t[1];
                b[2*np+1][0] = t[2]; b[2*np+1][1] = t[3];
            }
            #pragma unroll
            for (int mi = 0; mi < 4; mi++)
                #pragma unroll
                for (int ni = 0; ni < 4; ni++)
                    mma_f16(c[mi][ni], a[mi], b[ni]);
        }
        st++; if (st >= 3) st = 0;
    }

    // ------------------------------ epilogue --------------------------------
    #pragma unroll
    for (int mi = 0; mi < 4; mi++) {
        #pragma unroll
        for (int ni = 0; ni < 4; ni++) {
            const int col = n0 + warpn * 32 + ni * 8 + 2 * tig;
            float bx = 0.f, by = 0.f;
            if (bias) { bx = bias[col]; by = bias[col + 1]; }
            #pragma unroll
            for (int h = 0; h < 2; h++) {
                const int row = m0 + warpm * 64 + mi * 16 + gid + h * 8;
                float v0 = c[mi][ni][2*h + 0] + bx;
                float v1 = c[mi][ni][2*h + 1] + by;
                if (act == 1) {
                    v0 = 0.5f * v0 * (1.0f + erff(v0 * 0.70710678118654752f));
                    v1 = 0.5f * v1 * (1.0f + erff(v1 * 0.70710678118654752f));
                } else if (act == 2) {
                    v0 = fmaxf(v0, 0.f); v1 = fmaxf(v1, 0.f);
                } else if (act == 3) {
                    v0 = 1.f / (1.f + expf(-v0)); v1 = 1.f / (1.f + expf(-v1));
                }
                const long long g = (long long)row * ldc + col;
                if (sizeof(CT) == 2) {
                    *(__half2*)((__half*)C + g) = __floats2half2_rn(v0, v1);
                } else {
                    if (resid) {
                        float2 q = *(const float2*)(resid + g);
                        v0 += q.x; v1 += q.y;
                    }
                    float2 o; o.x = v0; o.y = v1;
                    *(float2*)((float*)C + g) = o;
                }
            }
        }
    }
}

// ----------------------- fused flash attention ------------------------------
// ctx[b, q, h*64+d] = softmax(Q K^T) V   (scale pre-folded into Q weights)
__global__ __launch_bounds__(256)
void flash_attn(const __half* __restrict__ QKV, int ld, __half* __restrict__ ctx)
{
    extern __shared__ char sm[];
    char* Qs = sm;                       // 16 KB
    char* Kb[2] = { sm + 16384, sm + 32768 };
    char* Vb[2] = { sm + 24576, sm + 40960 };

    const int tid = threadIdx.x, wid = tid >> 5, lane = tid & 31;
    const int gid = lane >> 2, tig = lane & 3;
    const int qt = blockIdx.x, bh = blockIdx.y;
    const int b = bh >> 4, hh = bh & 15;

    const __half* Qg = QKV + ((size_t)(b * 1024 + qt * 128) * ld + hh * 64);
    const __half* Kg = QKV + ((size_t)b * 1024 * ld + 1024 + hh * 64);
    const __half* Vg = QKV + ((size_t)b * 1024 * ld + 2048 + hh * 64);

    #pragma unroll
    for (int i = 0; i < 4; i++) {
        int id = tid + i * 256;
        int r = id >> 3, cc = id & 7;
        cp16(smem_addr(Qs + sw128(r * 128 + cc * 16)), Qg + (size_t)r * ld + cc * 8);
    }
    cp_commit();

    auto stage_kv = [&](int kt, int buf) {
        #pragma unroll
        for (int i = 0; i < 2; i++) {
            int id = tid + i * 256;
            int r = id >> 3, cc = id & 7;
            int swb = sw128(r * 128 + cc * 16);
            cp16(smem_addr(Kb[buf] + swb), Kg + (size_t)(kt * 64 + r) * ld + cc * 8);
            cp16(smem_addr(Vb[buf] + swb), Vg + (size_t)(kt * 64 + r) * ld + cc * 8);
        }
    };
    stage_kv(0, 0);
    cp_commit();

    cp_wait<1>();
    __syncthreads();

    uint32_t qf[4][4];
    #pragma unroll
    for (int ks = 0; ks < 4; ks++) {
        int row = wid * 16 + (lane & 15);
        int colb = ks * 32 + ((lane & 16) ? 16 : 0);
        ldmx4(qf[ks], smem_addr(Qs + sw128(row * 128 + colb)));
    }

    float m0 = -1e30f, m1 = -1e30f, l0 = 0.f, l1 = 0.f;
    float o[8][4];
    #pragma unroll
    for (int nt = 0; nt < 8; nt++)
        #pragma unroll
        for (int e = 0; e < 4; e++) o[nt][e] = 0.f;

    for (int kt = 0; kt < 16; kt++) {
        const int buf = kt & 1;
        if (kt + 1 < 16) { stage_kv(kt + 1, buf ^ 1); cp_commit(); cp_wait<1>(); }
        else             { cp_wait<0>(); }
        __syncthreads();

        float s[8][4];
        #pragma unroll
        for (int nt = 0; nt < 8; nt++)
            #pragma unroll
            for (int e = 0; e < 4; e++) s[nt][e] = 0.f;

        #pragma unroll
        for (int ks = 0; ks < 4; ks++) {
            uint32_t kb[8][2];
            #pragma unroll
            for (int ntp = 0; ntp < 4; ntp++) {
                int row = ntp * 16 + (lane & 7) + ((lane & 16) ? 8 : 0);
                int colb = ks * 32 + ((lane & 8) ? 16 : 0);
                uint32_t t[4];
                ldmx4(t, smem_addr(Kb[buf] + sw128(row * 128 + colb)));
                kb[2*ntp][0] = t[0]; kb[2*ntp][1] = t[1];
                kb[2*ntp+1][0] = t[2]; kb[2*ntp+1][1] = t[3];
            }
            #pragma unroll
            for (int nt = 0; nt < 8; nt++)
                mma_f16(s[nt], qf[ks], kb[nt]);
        }

        float mc0 = -1e30f, mc1 = -1e30f;
        #pragma unroll
        for (int nt = 0; nt < 8; nt++) {
            mc0 = fmaxf(mc0, fmaxf(s[nt][0], s[nt][1]));
            mc1 = fmaxf(mc1, fmaxf(s[nt][2], s[nt][3]));
        }
        mc0 = fmaxf(mc0, __shfl_xor_sync(0xffffffffu, mc0, 1));
        mc0 = fmaxf(mc0, __shfl_xor_sync(0xffffffffu, mc0, 2));
        mc1 = fmaxf(mc1, __shfl_xor_sync(0xffffffffu, mc1, 1));
        mc1 = fmaxf(mc1, __shfl_xor_sync(0xffffffffu, mc1, 2));
        float mn0 = fmaxf(m0, mc0), mn1 = fmaxf(m1, mc1);
        float sc0 = __expf(m0 - mn0), sc1 = __expf(m1 - mn1);
        m0 = mn0; m1 = mn1;

        float rs0 = 0.f, rs1 = 0.f;
        uint32_t pf[8][2];
        #pragma unroll
        for (int nt = 0; nt < 8; nt++) {
            float p0 = __expf(s[nt][0] - mn0);
            float p1 = __expf(s[nt][1] - mn0);
            float p2 = __expf(s[nt][2] - mn1);
            float p3 = __expf(s[nt][3] - mn1);
            rs0 += p0 + p1; rs1 += p2 + p3;
            pf[nt][0] = pack_h2(p0, p1);
            pf[nt][1] = pack_h2(p2, p3);
        }
        rs0 += __shfl_xor_sync(0xffffffffu, rs0, 1);
        rs0 += __shfl_xor_sync(0xffffffffu, rs0, 2);
        rs1 += __shfl_xor_sync(0xffffffffu, rs1, 1);
        rs1 += __shfl_xor_sync(0xffffffffu, rs1, 2);
        l0 = l0 * sc0 + rs0;
        l1 = l1 * sc1 + rs1;
        #pragma unroll
        for (int nt = 0; nt < 8; nt++) {
            o[nt][0] *= sc0; o[nt][1] *= sc0;
            o[nt][2] *= sc1; o[nt][3] *= sc1;
        }

        #pragma unroll
        for (int ks = 0; ks < 4; ks++) {
            uint32_t vb[8][2];
            #pragma unroll
            for (int ntp = 0; ntp < 4; ntp++) {
                int row = ks * 16 + (lane & 7) + ((lane & 8) ? 8 : 0);
                int colb = ntp * 32 + ((lane & 16) ? 16 : 0);
                uint32_t t[4];
                asm volatile("ldmatrix.sync.aligned.m8n8.x4.trans.shared.b16 {%0,%1,%2,%3}, [%4];"
                    : "=r"(t[0]), "=r"(t[1]), "=r"(t[2]), "=r"(t[3])
                    : "r"(smem_addr(Vb[buf] + sw128(row * 128 + colb))));
                vb[2*ntp][0] = t[0]; vb[2*ntp][1] = t[1];
                vb[2*ntp+1][0] = t[2]; vb[2*ntp+1][1] = t[3];
            }
            uint32_t a[4] = { pf[2*ks][0], pf[2*ks][1], pf[2*ks+1][0], pf[2*ks+1][1] };
            #pragma unroll
            for (int nt = 0; nt < 8; nt++)
                mma_f16(o[nt], a, vb[nt]);
        }
        __syncthreads();
    }

    float inv0 = 1.f / l0, inv1 = 1.f / l1;
    const int row0 = b * 1024 + qt * 128 + wid * 16 + gid;
    #pragma unroll
    for (int nt = 0; nt < 8; nt++) {
        int col = hh * 64 + nt * 8 + 2 * tig;
        *(__half2*)(ctx + (size_t)row0 * 1024 + col) =
            __floats2half2_rn(o[nt][0] * inv0, o[nt][1] * inv0);
        *(__half2*)(ctx + (size_t)(row0 + 8) * 1024 + col) =
            __floats2half2_rn(o[nt][2] * inv1, o[nt][3] * inv1);
    }
}

// ---------------- single-launch preprocessing (all weights + x) -------------
#define PREP_BLOCKS 21516

__device__ __forceinline__ void tr_tile(const float* __restrict__ in, int ldi,
                                        __half* __restrict__ out, int ldo,
                                        float scale, int tile, int tilesx)
{
    __shared__ float t[32][33];
    const int bx = tile % tilesx, by = tile / tilesx;
    const int r0 = by * 32, c0 = bx * 32;
    const int tx = threadIdx.x & 31, ty = threadIdx.x >> 5;
    #pragma unroll
    for (int i = 0; i < 32; i += 8)
        t[ty + i][tx] = in[(long long)(r0 + ty + i) * ldi + c0 + tx];
    __syncthreads();
    #pragma unroll
    for (int i = 0; i < 32; i += 8)
        out[(long long)(c0 + ty + i) * ldo + r0 + tx] = __float2half(t[tx][ty + i] * scale);
}

__global__ __launch_bounds__(256)
void prep_kernel(const float* __restrict__ x, __half* __restrict__ xh,
                 const float* __restrict__ Wq, const float* __restrict__ Wk,
                 const float* __restrict__ Wv, const float* __restrict__ Wo,
                 const float* __restrict__ fw1, const float* __restrict__ fw2,
                 const float* __restrict__ gw1, const float* __restrict__ gw2,
                 __half* __restrict__ WqkvT, __half* __restrict__ WoT,
                 __half* __restrict__ fw1T, __half* __restrict__ fw2T,
                 __half* __restrict__ gw1T, __half* __restrict__ gw2T,
                 const float* __restrict__ bq, const float* __restrict__ bk,
                 const float* __restrict__ bv, float* __restrict__ bqkv)
{
    const int blk = blockIdx.x;
    if (blk < 8192) {
        const long long i = ((long long)blk * 256 + threadIdx.x) * 4;
        float4 v = *(const float4*)(x + i);
        __half2 a = __floats2half2_rn(v.x, v.y);
        __half2 b = __floats2half2_rn(v.z, v.w);
        *(uint2*)(xh + i) = make_uint2(*(uint32_t*)&a, *(uint32_t*)&b);
    } else if (blk < 9216) {
        tr_tile(Wq, Hsz, WqkvT, Hsz, 0.125f, blk - 8192, Hsz/32);
    } else if (blk < 10240) {
        tr_tile(Wk, Hsz, WqkvT + (size_t)Hsz*Hsz, Hsz, 1.f, blk - 9216, Hsz/32);
    } else if (blk < 11264) {
        tr_tile(Wv, Hsz, WqkvT + (size_t)2*Hsz*Hsz, Hsz, 1.f, blk - 10240, Hsz/32);
    } else if (blk < 12288) {
        tr_tile(Wo, Hsz, WoT, Hsz, 1.f, blk - 11264, Hsz/32);
    } else if (blk < 16384) {
        tr_tile(fw1, HF, fw1T, Hsz, 1.f, blk - 12288, HF/32);
    } else if (blk < 20480) {
        tr_tile(fw2, Hsz, fw2T, HF, 1.f, blk - 16384, Hsz/32);
    } else if (blk < 20992) {
        tr_tile(gw1, HG, gw1T, Hsz, 1.f, blk - 20480, HG/32);
    } else if (blk < 21504) {
        tr_tile(gw2, Hsz, gw2T, HG, 1.f, blk - 20992, Hsz/32);
    } else {
        int i = (blk - 21504) * 256 + threadIdx.x;
        float v;
        if (i < 1024)      v = bq[i] * 0.125f;
        else if (i < 2048) v = bk[i - 1024];
        else               v = bv[i - 2048];
        bqkv[i] = v;
    }
}

// -------------------------- block reduce (256 thr) --------------------------
__device__ __forceinline__ float blk_sum256(float v)
{
    __shared__ float sm[8];
    const int lane = threadIdx.x & 31, w = threadIdx.x >> 5;
    #pragma unroll
    for (int o = 16; o; o >>= 1) v += __shfl_xor_sync(0xffffffffu, v, o);
    if (lane == 0) sm[w] = v;
    __syncthreads();
    if (w == 0) {
        float r = (lane < 8) ? sm[lane] : 0.f;
        #pragma unroll
        for (int o = 4; o; o >>= 1) r += __shfl_xor_sync(0xffffffffu, r, o);
        if (lane == 0) sm[0] = r;
    }
    __syncthreads();
    float r = sm[0];
    __syncthreads();
    return r;
}

// ------------------------------- adaLN --------------------------------------
__global__ __launch_bounds__(256)
void ada_ln_kernel(const float* __restrict__ in, const float* __restrict__ vol,
                   const float* __restrict__ w, const float* __restrict__ b,
                   const float* __restrict__ gamma, const float* __restrict__ beta,
                   const float* __restrict__ vsw, const float* __restrict__ vsb,
                   float* __restrict__ out, __half* __restrict__ outh)
{
    const long long row = blockIdx.x;
    const int t = threadIdx.x;
    float4 v = *(const float4*)(in + row * 1024 + t * 4);

    float mu = blk_sum256(v.x + v.y + v.z + v.w) * (1.f / 1024.f);
    float dx = v.x - mu, dy = v.y - mu, dz = v.z - mu, dw = v.w - mu;
    float var = blk_sum256(dx * dx + dy * dy + dz * dz + dw * dw) * (1.f / 1024.f);
    float inv = rsqrtf(var + 1e-5f);

    float vs = 1.f / (1.f + expf(-(vol[row] * (*vsw) + (*vsb))));
    float k1 = (1.f + vs) * (*gamma);
    float k0 = *beta;

    float4 w4 = *(const float4*)(w + t * 4);
    float4 b4 = *(const float4*)(b + t * 4);
    float4 o;
    o.x = (dx * inv * w4.x + b4.x) * k1 + k0;
    o.y = (dy * inv * w4.y + b4.y) * k1 + k0;
    o.z = (dz * inv * w4.z + b4.z) * k1 + k0;
    o.w = (dw * inv * w4.w + b4.w) * k1 + k0;
    *(float4*)(out + row * 1024 + t * 4) = o;
    __half2 ha = __floats2half2_rn(o.x, o.y);
    __half2 hb = __floats2half2_rn(o.z, o.w);
    *(uint2*)(outh + row * 1024 + t * 4) = make_uint2(*(uint32_t*)&ha, *(uint32_t*)&hb);
}

// -------- combine (x1*(2-g) + ffn*g) then adaLN2 -> out ----------------------
__global__ __launch_bounds__(256)
void combine_ada_ln_kernel(const float* __restrict__ x1, const float* __restrict__ f,
                           const float* __restrict__ g,  const float* __restrict__ vol,
                           const float* __restrict__ w,  const float* __restrict__ b,
                           const float* __restrict__ gamma, const float* __restrict__ beta,
                           const float* __restrict__ vsw, const float* __restrict__ vsb,
                           float* __restrict__ out)
{
    const long long row = blockIdx.x;
    const int t = threadIdx.x;
    float4 a  = *(const float4*)(x1 + row * 1024 + t * 4);
    float4 ff = *(const float4*)(f  + row * 1024 + t * 4);
    float4 gg = *(const float4*)(g  + row * 1024 + t * 4);

    float4 v;
    v.x = a.x * (2.f - gg.x) + ff.x * gg.x;
    v.y = a.y * (2.f - gg.y) + ff.y * gg.y;
    v.z = a.z * (2.f - gg.z) + ff.z * gg.z;
    v.w = a.w * (2.f - gg.w) + ff.w * gg.w;

    float mu = blk_sum256(v.x + v.y + v.z + v.w) * (1.f / 1024.f);
    float dx = v.x - mu, dy = v.y - mu, dz = v.z - mu, dw = v.w - mu;
    float var = blk_sum256(dx * dx + dy * dy + dz * dz + dw * dw) * (1.f / 1024.f);
    float inv = rsqrtf(var + 1e-5f);

    float vs = 1.f / (1.f + expf(-(vol[row] * (*vsw) + (*vsb))));
    float k1 = (1.f + vs) * (*gamma);
    float k0 = *beta;

    float4 w4 = *(const float4*)(w + t * 4);
    float4 b4 = *(const float4*)(b + t * 4);
    float4 o;
    o.x = (dx * inv * w4.x + b4.x) * k1 + k0;
    o.y = (dy * inv * w4.y + b4.y) * k1 + k0;
    o.z = (dz * inv * w4.z + b4.z) * k1 + k0;
    o.w = (dw * inv * w4.w + b4.w) * k1 + k0;
    *(float4*)(out + row * 1024 + t * 4) = o;
}

// ------------------------------ launcher ------------------------------------
#define SMEM_GEMM  98304
#define SMEM_FLASH 49152

extern "C" void kernel_launch(void* const* d_in, const int* in_sizes, int n_in,
                              void* d_out, int out_size)
{
    const float* x      = (const float*)d_in[0];
    const float* vol    = (const float*)d_in[1];
    const float* Wq     = (const float*)d_in[2];
    const float* bq     = (const float*)d_in[3];
    const float* Wk     = (const float*)d_in[4];
    const float* bk     = (const float*)d_in[5];
    const float* Wv     = (const float*)d_in[6];
    const float* bv     = (const float*)d_in[7];
    const float* Wo     = (const float*)d_in[8];
    const float* bo     = (const float*)d_in[9];
    const float* ln1w   = (const float*)d_in[10];
    const float* ln1b   = (const float*)d_in[11];
    const float* gamma1 = (const float*)d_in[12];
    const float* beta1  = (const float*)d_in[13];
    const float* vs1w   = (const float*)d_in[14];
    const float* vs1b   = (const float*)d_in[15];
    const float* fw1    = (const float*)d_in[16];
    const float* fb1    = (const float*)d_in[17];
    const float* fw2    = (const float*)d_in[18];
    const float* fb2    = (const float*)d_in[19];
    const float* gw1    = (const float*)d_in[20];
    const float* gb1    = (const float*)d_in[21];
    const float* gw2    = (const float*)d_in[22];
    const float* gb2    = (const float*)d_in[23];
    const float* ln2w   = (const float*)d_in[24];
    const float* ln2b   = (const float*)d_in[25];
    const float* gamma2 = (const float*)d_in[26];
    const float* beta2  = (const float*)d_in[27];
    const float* vs2w   = (const float*)d_in[28];
    const float* vs2b   = (const float*)d_in[29];
    float* out = (float*)d_out;

    __half *xh, *QKV, *ctx, *h, *g1, *x1h;
    float *xr, *x1, *f, *g, *bqkv;
    __half *WqkvT, *WoT, *fw1T, *fw2T, *gw1T, *gw2T;
    cudaGetSymbolAddress((void**)&xh,    g_xh);
    cudaGetSymbolAddress((void**)&QKV,   g_QKV);
    cudaGetSymbolAddress((void**)&ctx,   g_ctx);
    cudaGetSymbolAddress((void**)&xr,    g_xr);
    cudaGetSymbolAddress((void**)&x1,    g_x1);
    cudaGetSymbolAddress((void**)&x1h,   g_x1h);
    cudaGetSymbolAddress((void**)&h,     g_h);
    cudaGetSymbolAddress((void**)&f,     g_f);
    cudaGetSymbolAddress((void**)&g1,    g_g1);
    cudaGetSymbolAddress((void**)&g,     g_g);
    cudaGetSymbolAddress((void**)&WqkvT, g_WqkvT);
    cudaGetSymbolAddress((void**)&bqkv,  g_bqkv);
    cudaGetSymbolAddress((void**)&WoT,   g_WoT);
    cudaGetSymbolAddress((void**)&fw1T,  g_fw1T);
    cudaGetSymbolAddress((void**)&fw2T,  g_fw2T);
    cudaGetSymbolAddress((void**)&gw1T,  g_gw1T);
    cudaGetSymbolAddress((void**)&gw2T,  g_gw2T);

    cudaFuncSetAttribute((const void*)mma_gemm<__half>, cudaFuncAttributeMaxDynamicSharedMemorySize, SMEM_GEMM);
    cudaFuncSetAttribute((const void*)mma_gemm<float>,  cudaFuncAttributeMaxDynamicSharedMemorySize, SMEM_GEMM);
    cudaFuncSetAttribute((const void*)flash_attn,       cudaFuncAttributeMaxDynamicSharedMemorySize, SMEM_FLASH);

    // ---- ONE preprocessing launch: all transposes + bias3 + f2h ----
    prep_kernel<<<PREP_BLOCKS, 256>>>(x, xh, Wq, Wk, Wv, Wo, fw1, fw2, gw1, gw2,
                                      WqkvT, WoT, fw1T, fw2T, gw1T, gw2T,
                                      bq, bk, bv, bqkv);

    // ---- fused QKV projection (one GEMM, N=3072) ----
    mma_gemm<__half><<<dim3(24,64),256,SMEM_GEMM>>>(xh,Hsz, WqkvT,Hsz, QKV,H3, bqkv,nullptr, Hsz, 0);

    // ---- fused attention ----
    flash_attn<<<dim3(8, Bsz*NH), 256, SMEM_FLASH>>>(QKV, H3, ctx);

    // ---- O projection + residual ----
    mma_gemm<float><<<dim3(8,64),256,SMEM_GEMM>>>(ctx,Hsz, WoT,Hsz, xr,Hsz, bo,x, Hsz, 0);

    // ---- adaLN1 (fp32 + fp16 outputs) ----
    ada_ln_kernel<<<Mrows,256>>>(xr, vol, ln1w, ln1b, gamma1, beta1, vs1w, vs1b, x1, x1h);

    // ---- FFN ----
    mma_gemm<__half><<<dim3(32,64),256,SMEM_GEMM>>>(x1h,Hsz, fw1T,Hsz, h,HF,  fb1,nullptr, Hsz, 1);
    mma_gemm<float> <<<dim3(8,64), 256,SMEM_GEMM>>>(h,HF,   fw2T,HF,  f,Hsz, fb2,nullptr, HF,  0);

    // ---- gate ----
    mma_gemm<__half><<<dim3(4,64),256,SMEM_GEMM>>>(x1h,Hsz, gw1T,Hsz, g1,HG, gb1,nullptr, Hsz, 2);
    mma_gemm<float> <<<dim3(8,64),256,SMEM_GEMM>>>(g1,HG,   gw2T,HG,  g,Hsz, gb2,nullptr, HG,  3);

    // ---- combine + adaLN2 -> out ----
    combine_ada_ln_kernel<<<Mrows,256>>>(x1, f, g, vol, ln2w, ln2b, gamma2, beta2, vs2w, vs2b, out);
}

// round 15
// speedup vs baseline: 1.0023x; 1.0023x over previous
#include <cuda_runtime.h>
#include <cuda_bf16.h>
#include <cuda_fp16.h>
#include <math.h>
#include <stdint.h>

// ---------------------------------------------------------------------------
// EnhancedTransformerBlock  B=8 S=1024 H=1024 nh=16 hd=64
// fp16 mma.sync GEMMs (128x128, 3-stage cp.async, 1 sync/chunk, 2 CTA/SM)
// + fused flash-attn + 1-launch prep
// ---------------------------------------------------------------------------

#define Bsz   8
#define Ssz   1024
#define Hsz   1024
#define NH    16
#define HD    64
#define Mrows (Bsz*Ssz)          // 8192
#define HF    (4*Hsz)            // 4096
#define HG    (Hsz/2)            // 512
#define H3    (3*Hsz)            // 3072

// ------------------------- scratch (device globals) ------------------------
__device__ __half g_xh  [(size_t)Mrows*Hsz];
__device__ __half g_QKV [(size_t)Mrows*H3];       // packed Q|K|V rows
__device__ __half g_ctx [(size_t)Mrows*Hsz];
__device__ float  g_xr  [(size_t)Mrows*Hsz];
__device__ float  g_x1  [(size_t)Mrows*Hsz];
__device__ __half g_x1h [(size_t)Mrows*Hsz];
__device__ __half g_h   [(size_t)Mrows*HF];
__device__ float  g_f   [(size_t)Mrows*Hsz];
__device__ __half g_g1  [(size_t)Mrows*HG];
__device__ float  g_g   [(size_t)Mrows*Hsz];
// transposed fp16 weights ([N][K] K-major)
__device__ __half g_WqkvT[(size_t)H3*Hsz];        // rows: [Wq*0.125 | Wk | Wv]
__device__ float  g_bqkv [H3];
__device__ __half g_WoT [(size_t)Hsz*Hsz];
__device__ __half g_fw1T[(size_t)Hsz*HF];
__device__ __half g_fw2T[(size_t)HF*Hsz];
__device__ __half g_gw1T[(size_t)Hsz*HG];
__device__ __half g_gw2T[(size_t)HG*Hsz];

// ------------------------------ helpers ------------------------------------
__device__ __forceinline__ uint32_t pack_h2(float lo, float hi) {
    __half2 h = __floats2half2_rn(lo, hi);
    return *(uint32_t*)&h;
}
__device__ __forceinline__ void mma_f16(float* c, const uint32_t* a, const uint32_t* b) {
    asm volatile(
        "mma.sync.aligned.m16n8k16.row.col.f32.f16.f16.f32 "
        "{%0,%1,%2,%3}, {%4,%5,%6,%7}, {%8,%9}, {%0,%1,%2,%3};"
        : "+f"(c[0]), "+f"(c[1]), "+f"(c[2]), "+f"(c[3])
        : "r"(a[0]), "r"(a[1]), "r"(a[2]), "r"(a[3]), "r"(b[0]), "r"(b[1]));
}
__device__ __forceinline__ int sw128(int byte) {
    return byte ^ ((byte >> 3) & 0x70);
}
__device__ __forceinline__ uint32_t smem_addr(const void* p) {
    return (uint32_t)__cvta_generic_to_shared(p);
}
__device__ __forceinline__ void cp16(uint32_t dst, const void* src) {
    asm volatile("cp.async.cg.shared.global [%0], [%1], 16;" :: "r"(dst), "l"(src));
}
__device__ __forceinline__ void cp_commit() { asm volatile("cp.async.commit_group;" ::: "memory"); }
template<int N> __device__ __forceinline__ void cp_wait() {
    asm volatile("cp.async.wait_group %0;" :: "n"(N) : "memory");
}
__device__ __forceinline__ void ldmx4(uint32_t* r, uint32_t addr) {
    asm volatile("ldmatrix.sync.aligned.m8n8.x4.shared.b16 {%0,%1,%2,%3}, [%4];"
        : "=r"(r[0]), "=r"(r[1]), "=r"(r[2]), "=r"(r[3]) : "r"(addr));
}

// ----------------------------- FP16 GEMM -----------------------------------
// C[m,n] = act(sum_k A[m,k]*B[n,k] + bias[n]) (+resid)
// A fp16 [M,K] K-major, B fp16 [N,K] K-major; tile 128x128, k-chunk 64.
// 3-stage cp.async pipeline, one __syncthreads per chunk.
// act: 0 none, 1 gelu, 2 relu, 3 sigmoid
template<typename CT>
__global__ __launch_bounds__(256, 2)
void mma_gemm(const __half* __restrict__ A, int lda,
              const __half* __restrict__ B, int ldb,
              CT* __restrict__ C, int ldc,
              const float* __restrict__ bias, const float* __restrict__ resid,
              int K, int act)
{
    extern __shared__ char sm[];   // 3 stages x (16KB A + 16KB B)

    const int tid = threadIdx.x, wid = tid >> 5, lane = tid & 31;
    const int gid = lane >> 2, tig = lane & 3;
    const int warpm = wid & 1, warpn = wid >> 1;

    const int m0 = blockIdx.y * 128;
    const int n0 = blockIdx.x * 128;

    float c[4][4][4];
    #pragma unroll
    for (int mi = 0; mi < 4; mi++)
        #pragma unroll
        for (int ni = 0; ni < 4; ni++)
            #pragma unroll
            for (int e = 0; e < 4; e++) c[mi][ni][e] = 0.f;

    // ---- hoisted staging addresses ----
    const int sr = tid >> 3, scq = tid & 7;     // row base 0..31, 16B col 0..7
    const __half* Ap[4]; const __half* Bp[4]; int swb[4];
    #pragma unroll
    for (int i = 0; i < 4; i++) {
        const int r = sr + i * 32;
        Ap[i]  = A + (size_t)(m0 + r) * lda + scq * 8;
        Bp[i]  = B + (size_t)(n0 + r) * ldb + scq * 8;
        swb[i] = sw128(r * 128 + scq * 16);
    }
    const uint32_t smem_base = smem_addr(sm);

    auto stage = [&](int kt, int st) {
        const uint32_t sa = smem_base + st * 32768;
        #pragma unroll
        for (int i = 0; i < 4; i++) {
            cp16(sa + swb[i],         Ap[i] + kt);
            cp16(sa + 16384 + swb[i], Bp[i] + kt);
        }
        cp_commit();
    };

    const int nch = K >> 6;
    stage(0, 0);
    stage(64, 1);

    int st = 0;                                  // stage index of current chunk
    for (int ch = 0; ch < nch; ch++) {
        if (ch < nch - 1) cp_wait<1>(); else cp_wait<0>();
        __syncthreads();
        if (ch + 2 < nch) {
            int ns = st + 2; if (ns >= 3) ns -= 3;
            stage((ch + 2) << 6, ns);
        }

        const char* As = sm + st * 32768;
        const char* Bs = As + 16384;
        #pragma unroll
        for (int ks = 0; ks < 4; ks++) {
            uint32_t a[4][4], b[4][2];
            #pragma unroll
            for (int mi = 0; mi < 4; mi++) {
                int row = warpm * 64 + mi * 16 + (lane & 15);
                int colb = ks * 32 + ((lane & 16) ? 16 : 0);
                ldmx4(a[mi], smem_addr(As + sw128(row * 128 + colb)));
            }
            #pragma unroll
            for (int np = 0; np < 2; np++) {
                int row = warpn * 32 + np * 16 + (lane & 7) + ((lane & 16) ? 8 : 0);
                int colb = ks * 32 + ((lane & 8) ? 16 : 0);
                uint32_t t[4];
                ldmx4(t, smem_addr(Bs + sw128(row * 128 + colb)));
                b[2*np][0] = t[0]; b[2*np][1] = t[1];
                b[2*np+1][0] = t[2]; b[2*np+1][1] = t[3];
            }
            #pragma unroll
            for (int mi = 0; mi < 4; mi++)
                #pragma unroll
                for (int ni = 0; ni < 4; ni++)
                    mma_f16(c[mi][ni], a[mi], b[ni]);
        }
        st++; if (st >= 3) st = 0;
    }

    // ------------------------------ epilogue --------------------------------
    #pragma unroll
    for (int mi = 0; mi < 4; mi++) {
        #pragma unroll
        for (int ni = 0; ni < 4; ni++) {
            const int col = n0 + warpn * 32 + ni * 8 + 2 * tig;
            float bx = 0.f, by = 0.f;
            if (bias) { bx = bias[col]; by = bias[col + 1]; }
            #pragma unroll
            for (int h = 0; h < 2; h++) {
                const int row = m0 + warpm * 64 + mi * 16 + gid + h * 8;
                float v0 = c[mi][ni][2*h + 0] + bx;
                float v1 = c[mi][ni][2*h + 1] + by;
                if (act == 1) {
                    v0 = 0.5f * v0 * (1.0f + erff(v0 * 0.70710678118654752f));
                    v1 = 0.5f * v1 * (1.0f + erff(v1 * 0.70710678118654752f));
                } else if (act == 2) {
                    v0 = fmaxf(v0, 0.f); v1 = fmaxf(v1, 0.f);
                } else if (act == 3) {
                    v0 = 1.f / (1.f + expf(-v0)); v1 = 1.f / (1.f + expf(-v1));
                }
                const long long g = (long long)row * ldc + col;
                if (sizeof(CT) == 2) {
                    *(__half2*)((__half*)C + g) = __floats2half2_rn(v0, v1);
                } else {
                    if (resid) {
                        float2 q = *(const float2*)(resid + g);
                        v0 += q.x; v1 += q.y;
                    }
                    float2 o; o.x = v0; o.y = v1;
                    *(float2*)((float*)C + g) = o;
                }
            }
        }
    }
}

// ----------------------- fused flash attention ------------------------------
// ctx[b, q, h*64+d] = softmax(Q K^T) V   (scale pre-folded into Q weights)
__global__ __launch_bounds__(256)
void flash_attn(const __half* __restrict__ QKV, int ld, __half* __restrict__ ctx)
{
    extern __shared__ char sm[];
    char* Qs = sm;                       // 16 KB
    char* Kb[2] = { sm + 16384, sm + 32768 };
    char* Vb[2] = { sm + 24576, sm + 40960 };

    const int tid = threadIdx.x, wid = tid >> 5, lane = tid & 31;
    const int gid = lane >> 2, tig = lane & 3;
    const int qt = blockIdx.x, bh = blockIdx.y;
    const int b = bh >> 4, hh = bh & 15;

    const __half* Qg = QKV + ((size_t)(b * 1024 + qt * 128) * ld + hh * 64);
    const __half* Kg = QKV + ((size_t)b * 1024 * ld + 1024 + hh * 64);
    const __half* Vg = QKV + ((size_t)b * 1024 * ld + 2048 + hh * 64);

    #pragma unroll
    for (int i = 0; i < 4; i++) {
        int id = tid + i * 256;
        int r = id >> 3, cc = id & 7;
        cp16(smem_addr(Qs + sw128(r * 128 + cc * 16)), Qg + (size_t)r * ld + cc * 8);
    }
    cp_commit();

    auto stage_kv = [&](int kt, int buf) {
        #pragma unroll
        for (int i = 0; i < 2; i++) {
            int id = tid + i * 256;
            int r = id >> 3, cc = id & 7;
            int swb = sw128(r * 128 + cc * 16);
            cp16(smem_addr(Kb[buf] + swb), Kg + (size_t)(kt * 64 + r) * ld + cc * 8);
            cp16(smem_addr(Vb[buf] + swb), Vg + (size_t)(kt * 64 + r) * ld + cc * 8);
        }
    };
    stage_kv(0, 0);
    cp_commit();

    cp_wait<1>();
    __syncthreads();

    uint32_t qf[4][4];
    #pragma unroll
    for (int ks = 0; ks < 4; ks++) {
        int row = wid * 16 + (lane & 15);
        int colb = ks * 32 + ((lane & 16) ? 16 : 0);
        ldmx4(qf[ks], smem_addr(Qs + sw128(row * 128 + colb)));
    }

    float m0 = -1e30f, m1 = -1e30f, l0 = 0.f, l1 = 0.f;
    float o[8][4];
    #pragma unroll
    for (int nt = 0; nt < 8; nt++)
        #pragma unroll
        for (int e = 0; e < 4; e++) o[nt][e] = 0.f;

    for (int kt = 0; kt < 16; kt++) {
        const int buf = kt & 1;
        if (kt + 1 < 16) { stage_kv(kt + 1, buf ^ 1); cp_commit(); cp_wait<1>(); }
        else             { cp_wait<0>(); }
        __syncthreads();

        float s[8][4];
        #pragma unroll
        for (int nt = 0; nt < 8; nt++)
            #pragma unroll
            for (int e = 0; e < 4; e++) s[nt][e] = 0.f;

        #pragma unroll
        for (int ks = 0; ks < 4; ks++) {
            uint32_t kb[8][2];
            #pragma unroll
            for (int ntp = 0; ntp < 4; ntp++) {
                int row = ntp * 16 + (lane & 7) + ((lane & 16) ? 8 : 0);
                int colb = ks * 32 + ((lane & 8) ? 16 : 0);
                uint32_t t[4];
                ldmx4(t, smem_addr(Kb[buf] + sw128(row * 128 + colb)));
                kb[2*ntp][0] = t[0]; kb[2*ntp][1] = t[1];
                kb[2*ntp+1][0] = t[2]; kb[2*ntp+1][1] = t[3];
            }
            #pragma unroll
            for (int nt = 0; nt < 8; nt++)
                mma_f16(s[nt], qf[ks], kb[nt]);
        }

        float mc0 = -1e30f, mc1 = -1e30f;
        #pragma unroll
        for (int nt = 0; nt < 8; nt++) {
            mc0 = fmaxf(mc0, fmaxf(s[nt][0], s[nt][1]));
            mc1 = fmaxf(mc1, fmaxf(s[nt][2], s[nt][3]));
        }
        mc0 = fmaxf(mc0, __shfl_xor_sync(0xffffffffu, mc0, 1));
        mc0 = fmaxf(mc0, __shfl_xor_sync(0xffffffffu, mc0, 2));
        mc1 = fmaxf(mc1, __shfl_xor_sync(0xffffffffu, mc1, 1));
        mc1 = fmaxf(mc1, __shfl_xor_sync(0xffffffffu, mc1, 2));
        float mn0 = fmaxf(m0, mc0), mn1 = fmaxf(m1, mc1);
        float sc0 = __expf(m0 - mn0), sc1 = __expf(m1 - mn1);
        m0 = mn0; m1 = mn1;

        float rs0 = 0.f, rs1 = 0.f;
        uint32_t pf[8][2];
        #pragma unroll
        for (int nt = 0; nt < 8; nt++) {
            float p0 = __expf(s[nt][0] - mn0);
            float p1 = __expf(s[nt][1] - mn0);
            float p2 = __expf(s[nt][2] - mn1);
            float p3 = __expf(s[nt][3] - mn1);
            rs0 += p0 + p1; rs1 += p2 + p3;
            pf[nt][0] = pack_h2(p0, p1);
            pf[nt][1] = pack_h2(p2, p3);
        }
        rs0 += __shfl_xor_sync(0xffffffffu, rs0, 1);
        rs0 += __shfl_xor_sync(0xffffffffu, rs0, 2);
        rs1 += __shfl_xor_sync(0xffffffffu, rs1, 1);
        rs1 += __shfl_xor_sync(0xffffffffu, rs1, 2);
        l0 = l0 * sc0 + rs0;
        l1 = l1 * sc1 + rs1;
        #pragma unroll
        for (int nt = 0; nt < 8; nt++) {
            o[nt][0] *= sc0; o[nt][1] *= sc0;
            o[nt][2] *= sc1; o[nt][3] *= sc1;
        }

        #pragma unroll
        for (int ks = 0; ks < 4; ks++) {
            uint32_t vb[8][2];
            #pragma unroll
            for (int ntp = 0; ntp < 4; ntp++) {
                int row = ks * 16 + (lane & 7) + ((lane & 8) ? 8 : 0);
                int colb = ntp * 32 + ((lane & 16) ? 16 : 0);
                uint32_t t[4];
                asm volatile("ldmatrix.sync.aligned.m8n8.x4.trans.shared.b16 {%0,%1,%2,%3}, [%4];"
                    : "=r"(t[0]), "=r"(t[1]), "=r"(t[2]), "=r"(t[3])
                    : "r"(smem_addr(Vb[buf] + sw128(row * 128 + colb))));
                vb[2*ntp][0] = t[0]; vb[2*ntp][1] = t[1];
                vb[2*ntp+1][0] = t[2]; vb[2*ntp+1][1] = t[3];
            }
            uint32_t a[4] = { pf[2*ks][0], pf[2*ks][1], pf[2*ks+1][0], pf[2*ks+1][1] };
            #pragma unroll
            for (int nt = 0; nt < 8; nt++)
                mma_f16(o[nt], a, vb[nt]);
        }
        __syncthreads();
    }

    float inv0 = 1.f / l0, inv1 = 1.f / l1;
    const int row0 = b * 1024 + qt * 128 + wid * 16 + gid;
    #pragma unroll
    for (int nt = 0; nt < 8; nt++) {
        int col = hh * 64 + nt * 8 + 2 * tig;
        *(__half2*)(ctx + (size_t)row0 * 1024 + col) =
            __floats2half2_rn(o[nt][0] * inv0, o[nt][1] * inv0);
        *(__half2*)(ctx + (size_t)(row0 + 8) * 1024 + col) =
            __floats2half2_rn(o[nt][2] * inv1, o[nt][3] * inv1);
    }
}

// ---------------- single-launch preprocessing (all weights + x) -------------
#define PREP_BLOCKS 21516

__device__ __forceinline__ void tr_tile(const float* __restrict__ in, int ldi,
                                        __half* __restrict__ out, int ldo,
                                        float scale, int tile, int tilesx)
{
    __shared__ float t[32][33];
    const int bx = tile % tilesx, by = tile / tilesx;
    const int r0 = by * 32, c0 = bx * 32;
    const int tx = threadIdx.x & 31, ty = threadIdx.x >> 5;
    #pragma unroll
    for (int i = 0; i < 32; i += 8)
        t[ty + i][tx] = in[(long long)(r0 + ty + i) * ldi + c0 + tx];
    __syncthreads();
    #pragma unroll
    for (int i = 0; i < 32; i += 8)
        out[(long long)(c0 + ty + i) * ldo + r0 + tx] = __float2half(t[tx][ty + i] * scale);
}

__global__ __launch_bounds__(256)
void prep_kernel(const float* __restrict__ x, __half* __restrict__ xh,
                 const float* __restrict__ Wq, const float* __restrict__ Wk,
                 const float* __restrict__ Wv, const float* __restrict__ Wo,
                 const float* __restrict__ fw1, const float* __restrict__ fw2,
                 const float* __restrict__ gw1, const float* __restrict__ gw2,
                 __half* __restrict__ WqkvT, __half* __restrict__ WoT,
                 __half* __restrict__ fw1T, __half* __restrict__ fw2T,
                 __half* __restrict__ gw1T, __half* __restrict__ gw2T,
                 const float* __restrict__ bq, const float* __restrict__ bk,
                 const float* __restrict__ bv, float* __restrict__ bqkv)
{
    const int blk = blockIdx.x;
    if (blk < 8192) {
        const long long i = ((long long)blk * 256 + threadIdx.x) * 4;
        float4 v = *(const float4*)(x + i);
        __half2 a = __floats2half2_rn(v.x, v.y);
        __half2 b = __floats2half2_rn(v.z, v.w);
        *(uint2*)(xh + i) = make_uint2(*(uint32_t*)&a, *(uint32_t*)&b);
    } else if (blk < 9216) {
        tr_tile(Wq, Hsz, WqkvT, Hsz, 0.125f, blk - 8192, Hsz/32);
    } else if (blk < 10240) {
        tr_tile(Wk, Hsz, WqkvT + (size_t)Hsz*Hsz, Hsz, 1.f, blk - 9216, Hsz/32);
    } else if (blk < 11264) {
        tr_tile(Wv, Hsz, WqkvT + (size_t)2*Hsz*Hsz, Hsz, 1.f, blk - 10240, Hsz/32);
    } else if (blk < 12288) {
        tr_tile(Wo, Hsz, WoT, Hsz, 1.f, blk - 11264, Hsz/32);
    } else if (blk < 16384) {
        tr_tile(fw1, HF, fw1T, Hsz, 1.f, blk - 12288, HF/32);
    } else if (blk < 20480) {
        tr_tile(fw2, Hsz, fw2T, HF, 1.f, blk - 16384, Hsz/32);
    } else if (blk < 20992) {
        tr_tile(gw1, HG, gw1T, Hsz, 1.f, blk - 20480, HG/32);
    } else if (blk < 21504) {
        tr_tile(gw2, Hsz, gw2T, HG, 1.f, blk - 20992, Hsz/32);
    } else {
        int i = (blk - 21504) * 256 + threadIdx.x;
        float v;
        if (i < 1024)      v = bq[i] * 0.125f;
        else if (i < 2048) v = bk[i - 1024];
        else               v = bv[i - 2048];
        bqkv[i] = v;
    }
}

// -------------------------- block reduce (256 thr) --------------------------
__device__ __forceinline__ float blk_sum256(float v)
{
    __shared__ float sm[8];
    const int lane = threadIdx.x & 31, w = threadIdx.x >> 5;
    #pragma unroll
    for (int o = 16; o; o >>= 1) v += __shfl_xor_sync(0xffffffffu, v, o);
    if (lane == 0) sm[w] = v;
    __syncthreads();
    if (w == 0) {
        float r = (lane < 8) ? sm[lane] : 0.f;
        #pragma unroll
        for (int o = 4; o; o >>= 1) r += __shfl_xor_sync(0xffffffffu, r, o);
        if (lane == 0) sm[0] = r;
    }
    __syncthreads();
    float r = sm[0];
    __syncthreads();
    return r;
}

// ------------------------------- adaLN --------------------------------------
__global__ __launch_bounds__(256)
void ada_ln_kernel(const float* __restrict__ in, const float* __restrict__ vol,
                   const float* __restrict__ w, const float* __restrict__ b,
                   const float* __restrict__ gamma, const float* __restrict__ beta,
                   const float* __restrict__ vsw, const float* __restrict__ vsb,
                   float* __restrict__ out, __half* __restrict__ outh)
{
    const long long row = blockIdx.x;
    const int t = threadIdx.x;
    float4 v = *(const float4*)(in + row * 1024 + t * 4);

    float mu = blk_sum256(v.x + v.y + v.z + v.w) * (1.f / 1024.f);
    float dx = v.x - mu, dy = v.y - mu, dz = v.z - mu, dw = v.w - mu;
    float var = blk_sum256(dx * dx + dy * dy + dz * dz + dw * dw) * (1.f / 1024.f);
    float inv = rsqrtf(var + 1e-5f);

    float vs = 1.f / (1.f + expf(-(vol[row] * (*vsw) + (*vsb))));
    float k1 = (1.f + vs) * (*gamma);
    float k0 = *beta;

    float4 w4 = *(const float4*)(w + t * 4);
    float4 b4 = *(const float4*)(b + t * 4);
    float4 o;
    o.x = (dx * inv * w4.x + b4.x) * k1 + k0;
    o.y = (dy * inv * w4.y + b4.y) * k1 + k0;
    o.z = (dz * inv * w4.z + b4.z) * k1 + k0;
    o.w = (dw * inv * w4.w + b4.w) * k1 + k0;
    *(float4*)(out + row * 1024 + t * 4) = o;
    __half2 ha = __floats2half2_rn(o.x, o.y);
    __half2 hb = __floats2half2_rn(o.z, o.w);
    *(uint2*)(outh + row * 1024 + t * 4) = make_uint2(*(uint32_t*)&ha, *(uint32_t*)&hb);
}

// -------- combine (x1*(2-g) + ffn*g) then adaLN2 -> out ----------------------
__global__ __launch_bounds__(256)
void combine_ada_ln_kernel(const float* __restrict__ x1, const float* __restrict__ f,
                           const float* __restrict__ g,  const float* __restrict__ vol,
                           const float* __restrict__ w,  const float* __restrict__ b,
                           const float* __restrict__ gamma, const float* __restrict__ beta,
                           const float* __restrict__ vsw, const float* __restrict__ vsb,
                           float* __restrict__ out)
{
    const long long row = blockIdx.x;
    const int t = threadIdx.x;
    float4 a  = *(const float4*)(x1 + row * 1024 + t * 4);
    float4 ff = *(const float4*)(f  + row * 1024 + t * 4);
    float4 gg = *(const float4*)(g  + row * 1024 + t * 4);

    float4 v;
    v.x = a.x * (2.f - gg.x) + ff.x * gg.x;
    v.y = a.y * (2.f - gg.y) + ff.y * gg.y;
    v.z = a.z * (2.f - gg.z) + ff.z * gg.z;
    v.w = a.w * (2.f - gg.w) + ff.w * gg.w;

    float mu = blk_sum256(v.x + v.y + v.z + v.w) * (1.f / 1024.f);
    float dx = v.x - mu, dy = v.y - mu, dz = v.z - mu, dw = v.w - mu;
    float var = blk_sum256(dx * dx + dy * dy + dz * dz + dw * dw) * (1.f / 1024.f);
    float inv = rsqrtf(var + 1e-5f);

    float vs = 1.f / (1.f + expf(-(vol[row] * (*vsw) + (*vsb))));
    float k1 = (1.f + vs) * (*gamma);
    float k0 = *beta;

    float4 w4 = *(const float4*)(w + t * 4);
    float4 b4 = *(const float4*)(b + t * 4);
    float4 o;
    o.x = (dx * inv * w4.x + b4.x) * k1 + k0;
    o.y = (dy * inv * w4.y + b4.y) * k1 + k0;
    o.z = (dz * inv * w4.z + b4.z) * k1 + k0;
    o.w = (dw * inv * w4.w + b4.w) * k1 + k0;
    *(float4*)(out + row * 1024 + t * 4) = o;
}

// ------------------------------ launcher ------------------------------------
#define SMEM_GEMM  98304
#define SMEM_FLASH 49152

extern "C" void kernel_launch(void* const* d_in, const int* in_sizes, int n_in,
                              void* d_out, int out_size)
{
    const float* x      = (const float*)d_in[0];
    const float* vol    = (const float*)d_in[1];
    const float* Wq     = (const float*)d_in[2];
    const float* bq     = (const float*)d_in[3];
    const float* Wk     = (const float*)d_in[4];
    const float* bk     = (const float*)d_in[5];
    const float* Wv     = (const float*)d_in[6];
    const float* bv     = (const float*)d_in[7];
    const float* Wo     = (const float*)d_in[8];
    const float* bo     = (const float*)d_in[9];
    const float* ln1w   = (const float*)d_in[10];
    const float* ln1b   = (const float*)d_in[11];
    const float* gamma1 = (const float*)d_in[12];
    const float* beta1  = (const float*)d_in[13];
    const float* vs1w   = (const float*)d_in[14];
    const float* vs1b   = (const float*)d_in[15];
    const float* fw1    = (const float*)d_in[16];
    const float* fb1    = (const float*)d_in[17];
    const float* fw2    = (const float*)d_in[18];
    const float* fb2    = (const float*)d_in[19];
    const float* gw1    = (const float*)d_in[20];
    const float* gb1    = (const float*)d_in[21];
    const float* gw2    = (const float*)d_in[22];
    const float* gb2    = (const float*)d_in[23];
    const float* ln2w   = (const float*)d_in[24];
    const float* ln2b   = (const float*)d_in[25];
    const float* gamma2 = (const float*)d_in[26];
    const float* beta2  = (const float*)d_in[27];
    const float* vs2w   = (const float*)d_in[28];
    const float* vs2b   = (const float*)d_in[29];
    float* out = (float*)d_out;

    __half *xh, *QKV, *ctx, *h, *g1, *x1h;
    float *xr, *x1, *f, *g, *bqkv;
    __half *WqkvT, *WoT, *fw1T, *fw2T, *gw1T, *gw2T;
    cudaGetSymbolAddress((void**)&xh,    g_xh);
    cudaGetSymbolAddress((void**)&QKV,   g_QKV);
    cudaGetSymbolAddress((void**)&ctx,   g_ctx);
    cudaGetSymbolAddress((void**)&xr,    g_xr);
    cudaGetSymbolAddress((void**)&x1,    g_x1);
    cudaGetSymbolAddress((void**)&x1h,   g_x1h);
    cudaGetSymbolAddress((void**)&h,     g_h);
    cudaGetSymbolAddress((void**)&f,     g_f);
    cudaGetSymbolAddress((void**)&g1,    g_g1);
    cudaGetSymbolAddress((void**)&g,     g_g);
    cudaGetSymbolAddress((void**)&WqkvT, g_WqkvT);
    cudaGetSymbolAddress((void**)&bqkv,  g_bqkv);
    cudaGetSymbolAddress((void**)&WoT,   g_WoT);
    cudaGetSymbolAddress((void**)&fw1T,  g_fw1T);
    cudaGetSymbolAddress((void**)&fw2T,  g_fw2T);
    cudaGetSymbolAddress((void**)&gw1T,  g_gw1T);
    cudaGetSymbolAddress((void**)&gw2T,  g_gw2T);

    cudaFuncSetAttribute((const void*)mma_gemm<__half>, cudaFuncAttributeMaxDynamicSharedMemorySize, SMEM_GEMM);
    cudaFuncSetAttribute((const void*)mma_gemm<float>,  cudaFuncAttributeMaxDynamicSharedMemorySize, SMEM_GEMM);
    cudaFuncSetAttribute((const void*)flash_attn,       cudaFuncAttributeMaxDynamicSharedMemorySize, SMEM_FLASH);

    // ---- ONE preprocessing launch: all transposes + bias3 + f2h ----
    prep_kernel<<<PREP_BLOCKS, 256>>>(x, xh, Wq, Wk, Wv, Wo, fw1, fw2, gw1, gw2,
                                      WqkvT, WoT, fw1T, fw2T, gw1T, gw2T,
                                      bq, bk, bv, bqkv);

    // ---- fused QKV projection (one GEMM, N=3072) ----
    mma_gemm<__half><<<dim3(24,64),256,SMEM_GEMM>>>(xh,Hsz, WqkvT,Hsz, QKV,H3, bqkv,nullptr, Hsz, 0);

    // ---- fused attention ----
    flash_attn<<<dim3(8, Bsz*NH), 256, SMEM_FLASH>>>(QKV, H3, ctx);

    // ---- O projection + residual ----
    mma_gemm<float><<<dim3(8,64),256,SMEM_GEMM>>>(ctx,Hsz, WoT,Hsz, xr,Hsz, bo,x, Hsz, 0);

    // ---- adaLN1 (fp32 + fp16 outputs) ----
    ada_ln_kernel<<<Mrows,256>>>(xr, vol, ln1w, ln1b, gamma1, beta1, vs1w, vs1b, x1, x1h);

    // ---- FFN ----
    mma_gemm<__half><<<dim3(32,64),256,SMEM_GEMM>>>(x1h,Hsz, fw1T,Hsz, h,HF,  fb1,nullptr, Hsz, 1);
    mma_gemm<float> <<<dim3(8,64), 256,SMEM_GEMM>>>(h,HF,   fw2T,HF,  f,Hsz, fb2,nullptr, HF,  0);

    // ---- gate ----
    mma_gemm<__half><<<dim3(4,64),256,SMEM_GEMM>>>(x1h,Hsz, gw1T,Hsz, g1,HG, gb1,nullptr, Hsz, 2);
    mma_gemm<float> <<<dim3(8,64),256,SMEM_GEMM>>>(g1,HG,   gw2T,HG,  g,Hsz, gb2,nullptr, HG,  3);

    // ---- combine + adaLN2 -> out ----
    combine_ada_ln_kernel<<<Mrows,256>>>(x1, f, g, vol, ln2w, ln2b, gamma2, beta2, vs2w, vs2b, out);
}